// round 4
// baseline (speedup 1.0000x reference)
#include <cuda_runtime.h>
#include <math.h>
#include <stdint.h>

#define BSZ 512
#define DSZ 256
#define EPSF 1e-8f
#define MARGINF 0.3f
#define UWF 0.05f

// ---------------------------------------------------------------------------
// scratch (__device__ globals; no cudaMalloc allowed)
// ---------------------------------------------------------------------------
__device__ unsigned long long g_pos[BSZ * 16];   // per (anchor, j-tile) packed max
__device__ unsigned long long g_neg[BSZ * 16];   // per (anchor, j-tile) packed min
__device__ float g_busum[128];                   // per-block clipped-U partial sums
__device__ float g_rowloss[8];
__device__ float g_rowvalid[8];
__device__ unsigned int g_rowctr[8];             // wrap at 16 (atomicInc ,15)
__device__ unsigned int g_ctr2;                  // wrap at 8  (atomicInc ,7)

// packed f32x2 FMA: d = a*b + d (lane-wise IEEE fma)
#define FMA2(d, a, b) \
    asm("fma.rn.f32x2 %0, %1, %2, %0;" : "+l"(d) : "l"(a), "l"(b))

__device__ __forceinline__ uint32_t smem_u32(const void* p) {
    uint32_t r;
    asm("{ .reg .u64 t; cvta.to.shared.u64 t, %1; cvt.u32.u64 %0, t; }"
        : "=r"(r) : "l"(p));
    return r;
}

// ---------------------------------------------------------------------------
// Single fused kernel. grid (16 j-tiles, 8 i-rows) = 128 blocks, 256 threads.
// ---------------------------------------------------------------------------
__global__ __launch_bounds__(256) void k_all(const float* __restrict__ E,
                                             const float* __restrict__ U,
                                             const int*   __restrict__ L,
                                             float* __restrict__ out) {
    __shared__ __align__(16) float As[32][68];   // [d_local][i_local]
    __shared__ __align__(16) float Bs[32][34];   // [d_local][j_local]
    __shared__ float sni[64], snj[32];
    __shared__ int   sli[64], slj[32];
    __shared__ float s_cd[128];                  // combined candidate dist
    __shared__ int   s_cj[128];                  // combined candidate j
    __shared__ int   s_cv[128];                  // valid flag
    __shared__ float s_cw[128];                  // pair Σ u² diff²
    __shared__ float s_al[64], s_av[64];
    __shared__ float s_red[8];
    __shared__ int   s_flag, s_flag2;

    const int t = threadIdx.x;
    const int row = blockIdx.y;
    const int i0 = row * 64;
    const int j0 = blockIdx.x * 32;
    const int bid = row * 16 + blockIdx.x;
    const int w = t >> 5, lane = t & 31;
    const int tx = t & 15;        // j-pair index
    const int ty = t >> 4;        // i-quad index
    const float4* E4 = (const float4*)E;
    const float4* U4 = (const float4*)U;

    // loader lanes
    const int ar = t >> 2;        // 0..63 : i row within tile
    const int aq = t & 3;         // float4 slot (and +4)
    const int br = t >> 3;        // 0..31 : j row within tile
    const int bq = t & 7;         // float4 slot

    if (t < 64) sli[t] = L[i0 + t];
    if (t < 32) slj[t] = L[j0 + t];

    // this block's clipped-U slice sum (1024 floats)
    float us;
    {
        float4 uv = U4[bid * 256 + t];
        float u0 = fminf(fmaxf(uv.x, 1e-6f), 1.f);
        float u1 = fminf(fmaxf(uv.y, 1e-6f), 1.f);
        float u2 = fminf(fmaxf(uv.z, 1e-6f), 1.f);
        float u3 = fminf(fmaxf(uv.w, 1e-6f), 1.f);
        us = (u0 + u1) + (u2 + u3);
    }

    // packed accumulators (low half = anchor 4ty / 4ty+2, high = +1 / +3)
    uint64_t acc0x = 0, acc0y = 0, acc1x = 0, acc1y = 0;
    float nA = 0.f, nB = 0.f;

    const uint32_t as_base = smem_u32(&As[0][4 * ty]);
    const uint32_t bs_base = smem_u32(&Bs[0][2 * tx]);

    // prefetch chunk 0
    float4 pa0 = E4[(i0 + ar) * 64 + aq];
    float4 pa1 = E4[(i0 + ar) * 64 + aq + 4];
    float4 pb0 = E4[(j0 + br) * 64 + bq];

#pragma unroll 1
    for (int ch = 0; ch < 8; ch++) {
        nA = fmaf(pa0.x, pa0.x, nA); nA = fmaf(pa0.y, pa0.y, nA);
        nA = fmaf(pa0.z, pa0.z, nA); nA = fmaf(pa0.w, pa0.w, nA);
        nA = fmaf(pa1.x, pa1.x, nA); nA = fmaf(pa1.y, pa1.y, nA);
        nA = fmaf(pa1.z, pa1.z, nA); nA = fmaf(pa1.w, pa1.w, nA);
        nB = fmaf(pb0.x, pb0.x, nB); nB = fmaf(pb0.y, pb0.y, nB);
        nB = fmaf(pb0.z, pb0.z, nB); nB = fmaf(pb0.w, pb0.w, nB);

        As[aq * 4 + 0][ar] = pa0.x;
        As[aq * 4 + 1][ar] = pa0.y;
        As[aq * 4 + 2][ar] = pa0.z;
        As[aq * 4 + 3][ar] = pa0.w;
        As[aq * 4 + 16][ar] = pa1.x;
        As[aq * 4 + 17][ar] = pa1.y;
        As[aq * 4 + 18][ar] = pa1.z;
        As[aq * 4 + 19][ar] = pa1.w;
        Bs[bq * 4 + 0][br] = pb0.x;
        Bs[bq * 4 + 1][br] = pb0.y;
        Bs[bq * 4 + 2][br] = pb0.z;
        Bs[bq * 4 + 3][br] = pb0.w;
        __syncthreads();

        if (ch < 7) {
            pa0 = E4[(i0 + ar) * 64 + (ch + 1) * 8 + aq];
            pa1 = E4[(i0 + ar) * 64 + (ch + 1) * 8 + aq + 4];
            pb0 = E4[(j0 + br) * 64 + (ch + 1) * 8 + bq];
        }

#pragma unroll
        for (int d = 0; d < 32; d++) {
            uint64_t a01, a23, bxy;
            asm("ld.shared.b64 %0, [%1];" : "=l"(a01) : "r"(as_base + d * (68 * 4)));
            asm("ld.shared.b64 %0, [%1];" : "=l"(a23) : "r"(as_base + d * (68 * 4) + 8));
            asm("ld.shared.b64 %0, [%1];" : "=l"(bxy) : "r"(bs_base + d * (34 * 4)));
            uint32_t bxi, byi;
            asm("mov.b64 {%0, %1}, %2;" : "=r"(bxi), "=r"(byi) : "l"(bxy));
            uint64_t bxx, byy;
            asm("mov.b64 %0, {%1, %1};" : "=l"(bxx) : "r"(bxi));
            asm("mov.b64 %0, {%1, %1};" : "=l"(byy) : "r"(byi));
            FMA2(acc0x, a01, bxx);
            FMA2(acc0y, a01, byy);
            FMA2(acc1x, a23, bxx);
            FMA2(acc1y, a23, byy);
        }
        __syncthreads();
    }

    // publish row norms
    nA += __shfl_xor_sync(0xffffffffu, nA, 1);
    nA += __shfl_xor_sync(0xffffffffu, nA, 2);
    if (aq == 0) sni[ar] = nA;
    nB += __shfl_xor_sync(0xffffffffu, nB, 1);
    nB += __shfl_xor_sync(0xffffffffu, nB, 2);
    nB += __shfl_xor_sync(0xffffffffu, nB, 4);
    if (bq == 0) snj[br] = nB;
    __syncthreads();

    // unpack dots
    float dt[4][2];
    {
        uint32_t lo, hi;
        asm("mov.b64 {%0, %1}, %2;" : "=r"(lo), "=r"(hi) : "l"(acc0x));
        dt[0][0] = __uint_as_float(lo); dt[1][0] = __uint_as_float(hi);
        asm("mov.b64 {%0, %1}, %2;" : "=r"(lo), "=r"(hi) : "l"(acc0y));
        dt[0][1] = __uint_as_float(lo); dt[1][1] = __uint_as_float(hi);
        asm("mov.b64 {%0, %1}, %2;" : "=r"(lo), "=r"(hi) : "l"(acc1x));
        dt[2][0] = __uint_as_float(lo); dt[3][0] = __uint_as_float(hi);
        asm("mov.b64 {%0, %1}, %2;" : "=r"(lo), "=r"(hi) : "l"(acc1y));
        dt[2][1] = __uint_as_float(lo); dt[3][1] = __uint_as_float(hi);
    }

    const float njx = snj[2 * tx], njy = snj[2 * tx + 1];
    const int   ljx = slj[2 * tx], ljy = slj[2 * tx + 1];
    const int   jgx = j0 + 2 * tx, jgy = jgx + 1;

#pragma unroll
    for (int r = 0; r < 4; r++) {
        const int gi = i0 + 4 * ty + r;
        const int la = sli[4 * ty + r];
        const float nir = sni[4 * ty + r];
        float d0 = sqrtf(fmaxf(nir + njx - 2.f * dt[r][0], 0.f)) + EPSF;
        float d1 = sqrtf(fmaxf(nir + njy - 2.f * dt[r][1], 0.f)) + EPSF;

        // pos: max dist, same label, j != i; tie -> lowest j (encode ~j)
        unsigned long long bp = 0ull;
        if (ljx == la && jgx != gi)
            bp = ((unsigned long long)__float_as_uint(d0) << 32) | (0xFFFFFFFFu - (unsigned)jgx);
        if (ljy == la && jgy != gi) {
            unsigned long long c =
                ((unsigned long long)__float_as_uint(d1) << 32) | (0xFFFFFFFFu - (unsigned)jgy);
            if (c > bp) bp = c;
        }
        // neg: min dist, different label; tie -> lowest j
        unsigned long long bn = ~0ull;
        if (ljx != la)
            bn = ((unsigned long long)__float_as_uint(d0) << 32) | (unsigned)jgx;
        if (ljy != la) {
            unsigned long long c =
                ((unsigned long long)__float_as_uint(d1) << 32) | (unsigned)jgy;
            if (c < bn) bn = c;
        }

#pragma unroll
        for (int off = 8; off; off >>= 1) {
            unsigned long long o = __shfl_down_sync(0xffffffffu, bp, off, 16);
            if (o > bp) bp = o;
            o = __shfl_down_sync(0xffffffffu, bn, off, 16);
            if (o < bn) bn = o;
        }
        if (tx == 0) {
            g_pos[gi * 16 + blockIdx.x] = bp;
            g_neg[gi * 16 + blockIdx.x] = bn;
        }
    }

    // u-sum reduce and store
#pragma unroll
    for (int off = 16; off; off >>= 1) us += __shfl_xor_sync(0xffffffffu, us, off);
    if (lane == 0) s_red[w] = us;
    __syncthreads();
    if (t == 0) {
        float s = ((s_red[0] + s_red[1]) + (s_red[2] + s_red[3]))
                + ((s_red[4] + s_red[5]) + (s_red[6] + s_red[7]));
        g_busum[bid] = s;
    }
    __threadfence();
    __syncthreads();
    if (t == 0) s_flag = (atomicInc(&g_rowctr[row], 15) == 15) ? 1 : 0;
    __syncthreads();
    if (!s_flag) return;
    __threadfence();

    // ======================= row finalize (last block of row) ================
    const int hw = t >> 4;        // half-warp id 0..15
    const int l16 = t & 15;

    // combine 16 tile partials per (anchor, side): 128 tasks, 8 per half-warp
    unsigned long long pp[8];
#pragma unroll
    for (int q = 0; q < 8; q++) {
        int task = hw * 8 + q;
        int a = task >> 1;
        int ia = i0 + a;
        pp[q] = (task & 1) ? g_neg[ia * 16 + l16] : g_pos[ia * 16 + l16];
    }
#pragma unroll
    for (int q = 0; q < 8; q++) {
        int task = hw * 8 + q;
        bool ismin = (task & 1);
        unsigned long long p = pp[q];
#pragma unroll
        for (int off = 8; off; off >>= 1) {
            unsigned long long o = __shfl_xor_sync(0xffffffffu, p, off, 16);
            if (ismin ? (o < p) : (o > p)) p = o;
        }
        if (l16 == 0) {
            bool valid = ismin ? (p != ~0ull) : (p != 0ull);
            s_cd[task] = __uint_as_float((uint32_t)(p >> 32));
            s_cj[task] = valid ? (ismin ? (int)(uint32_t)p
                                        : (int)(0xFFFFFFFFu - (uint32_t)p))
                               : 0;
            s_cv[task] = valid ? 1 : 0;
        }
    }
    __syncthreads();

    // pair dots: W = Σ_d u_i² (e_i - e_j)², one pair per half-warp pass
#pragma unroll 1
    for (int q = 0; q < 8; q++) {
        int task = hw * 8 + q;
        int ia = i0 + (task >> 1);
        int jx = s_cj[task];
        float W = 0.f;
#pragma unroll
        for (int k = 0; k < 16; k++) {
            int d = l16 + 16 * k;
            float uu = U[ia * DSZ + d];
            uu = fminf(fmaxf(uu, 1e-6f), 1.f);
            float diff = E[ia * DSZ + d] - E[jx * DSZ + d];
            W = fmaf(uu * uu, diff * diff, W);
        }
#pragma unroll
        for (int off = 8; off; off >>= 1)
            W += __shfl_xor_sync(0xffffffffu, W, off, 16);
        if (l16 == 0) s_cw[task] = W;
    }
    __syncthreads();

    // per-anchor loss
    if (t < 64) {
        float dp = s_cd[2 * t], dn = s_cd[2 * t + 1];
        bool valid = s_cv[2 * t] && s_cv[2 * t + 1];
        float wp = s_cw[2 * t], wn = s_cw[2 * t + 1];
        float up2 = wp / (dp * dp) + EPSF;
        float un2 = wn / (dn * dn) + EPSF;
        float sig = sqrtf(up2 + un2 + EPSF);
        float me = MARGINF + UWF * sig;
        float z = (dp - dn + me) / sig;
        float sp = fmaxf(z, 0.f) + log1pf(expf(-fabsf(z)));
        s_al[t] = valid ? sig * sp : 0.f;
        s_av[t] = valid ? 1.f : 0.f;
    }
    __syncthreads();
    if (t < 32) {
        float l = s_al[t] + s_al[t + 32];
        float v = s_av[t] + s_av[t + 32];
#pragma unroll
        for (int off = 16; off; off >>= 1) {
            l += __shfl_xor_sync(0xffffffffu, l, off);
            v += __shfl_xor_sync(0xffffffffu, v, off);
        }
        if (t == 0) { g_rowloss[row] = l; g_rowvalid[row] = v; }
    }
    __threadfence();
    __syncthreads();
    if (t == 0) s_flag2 = (atomicInc(&g_ctr2, 7) == 7) ? 1 : 0;
    __syncthreads();
    if (!s_flag2) return;
    __threadfence();

    // ======================= final scalar (globally last block) ==============
    {
        float u = (t < 128) ? g_busum[t] : 0.f;
        float l = (t < 8) ? g_rowloss[t] : 0.f;
        float v = (t < 8) ? g_rowvalid[t] : 0.f;
#pragma unroll
        for (int off = 16; off; off >>= 1) {
            u += __shfl_xor_sync(0xffffffffu, u, off);
            l += __shfl_xor_sync(0xffffffffu, l, off);
            v += __shfl_xor_sync(0xffffffffu, v, off);
        }
        if (lane == 0 && w < 4) {
            s_red[w] = u;
            s_al[w] = l;      // warps 1..3 contribute 0 to l/v
            s_av[w] = v;
        }
        __syncthreads();
        if (t == 0) {
            float Uu = (s_red[0] + s_red[1]) + (s_red[2] + s_red[3]);
            float Ll = s_al[0] + s_al[1] + s_al[2] + s_al[3];
            float Vv = s_av[0] + s_av[1] + s_av[2] + s_av[3];
            float total = Ll / fmaxf(Vv, 1.0f) + UWF * (Uu / (float)(BSZ * DSZ));
            if (isnan(total) || isinf(total)) total = 0.f;
            out[0] = total;
        }
    }
}

// ---------------------------------------------------------------------------
extern "C" void kernel_launch(void* const* d_in, const int* in_sizes, int n_in,
                              void* d_out, int out_size) {
    const float* E = (const float*)d_in[0];
    const float* U = (const float*)d_in[1];
    const int*   L = (const int*)d_in[2];
    float* out = (float*)d_out;

    k_all<<<dim3(16, 8), 256>>>(E, U, L, out);
}

// round 5
// speedup vs baseline: 1.3636x; 1.3636x over previous
#include <cuda_runtime.h>
#include <math.h>
#include <stdint.h>

#define BSZ 512
#define DSZ 256
#define EPSF 1e-8f
#define MARGINF 0.3f
#define UWF 0.05f

// ---------------------------------------------------------------------------
// scratch (__device__ globals; no cudaMalloc allowed)
// ---------------------------------------------------------------------------
__device__ unsigned long long g_pos[BSZ * 16];   // per (anchor, j-tile) packed max
__device__ unsigned long long g_neg[BSZ * 16];   // per (anchor, j-tile) packed min
__device__ float g_bl[128], g_bv[128], g_bu[128];
__device__ unsigned int g_ctr = 0;               // wraps via atomicInc(.,127)

// packed f32x2 FMA: d = a*b + d (lane-wise IEEE fma)
#define FMA2(d, a, b) \
    asm("fma.rn.f32x2 %0, %1, %2, %0;" : "+l"(d) : "l"(a), "l"(b))

__device__ __forceinline__ uint32_t smem_u32(const void* p) {
    uint32_t r;
    asm("{ .reg .u64 t; cvta.to.shared.u64 t, %1; cvt.u32.u64 %0, t; }"
        : "=r"(r) : "l"(p));
    return r;
}

// ---------------------------------------------------------------------------
// K1: 64(i) x 32(j) distance tiles, 128 threads, 4x4 register tile.
//     Gram trick + inline norms + per-tile hardest-pos/neg mining.
//     grid (16 j-tiles, 8 i-rows) = 128 blocks.
// ---------------------------------------------------------------------------
__global__ __launch_bounds__(128) void k_dist_mine(const float* __restrict__ E,
                                                   const int*   __restrict__ L) {
    __shared__ __align__(16) float As[32][68];   // [d_local][i_local] (64+pad)
    __shared__ __align__(16) float Bs[32][36];   // [d_local][j_local] (32+pad)
    __shared__ float sni[64], snj[32];
    __shared__ int   sli[64], slj[32];

    const int t = threadIdx.x;
    const int i0 = blockIdx.y * 64;
    const int j0 = blockIdx.x * 32;
    const int tx = t & 7;         // j-quad
    const int ty = t >> 3;        // i-quad (0..15)
    const float4* E4 = (const float4*)E;

    // loader lanes
    const int ar = t >> 1, ah = t & 1;   // A: 64 rows x 2 threads, 4 f4 each
    const int br = t >> 2, bh = t & 3;   // B: 32 rows x 4 threads, 2 f4 each

    if (t < 64) sli[t] = L[i0 + t];
    if (t < 32) slj[t] = L[j0 + t];

    // 8 packed accumulators: accP[c] = rows(4ty+0,+1) x col c ; accQ = rows +2,+3
    uint64_t accP[4] = {0, 0, 0, 0}, accQ[4] = {0, 0, 0, 0};
    float nA = 0.f, nB = 0.f;

    const uint32_t as_base = smem_u32(&As[0][4 * ty]);
    const uint32_t bs_base = smem_u32(&Bs[0][4 * tx]);

    float4 pa[4], pb[2];
#pragma unroll
    for (int k = 0; k < 4; k++) pa[k] = E4[(i0 + ar) * 64 + ah + 2 * k];
#pragma unroll
    for (int k = 0; k < 2; k++) pb[k] = E4[(j0 + br) * 64 + bh + 4 * k];

#pragma unroll 1
    for (int ch = 0; ch < 8; ch++) {
        // inline norm accumulation
#pragma unroll
        for (int k = 0; k < 4; k++) {
            nA = fmaf(pa[k].x, pa[k].x, nA); nA = fmaf(pa[k].y, pa[k].y, nA);
            nA = fmaf(pa[k].z, pa[k].z, nA); nA = fmaf(pa[k].w, pa[k].w, nA);
        }
#pragma unroll
        for (int k = 0; k < 2; k++) {
            nB = fmaf(pb[k].x, pb[k].x, nB); nB = fmaf(pb[k].y, pb[k].y, nB);
            nB = fmaf(pb[k].z, pb[k].z, nB); nB = fmaf(pb[k].w, pb[k].w, nB);
        }

        // stage (transpose) into smem
#pragma unroll
        for (int k = 0; k < 4; k++) {
            int q = ah + 2 * k;
            As[q * 4 + 0][ar] = pa[k].x;
            As[q * 4 + 1][ar] = pa[k].y;
            As[q * 4 + 2][ar] = pa[k].z;
            As[q * 4 + 3][ar] = pa[k].w;
        }
#pragma unroll
        for (int k = 0; k < 2; k++) {
            int q = bh + 4 * k;
            Bs[q * 4 + 0][br] = pb[k].x;
            Bs[q * 4 + 1][br] = pb[k].y;
            Bs[q * 4 + 2][br] = pb[k].z;
            Bs[q * 4 + 3][br] = pb[k].w;
        }
        __syncthreads();

        if (ch < 7) {  // prefetch next chunk (hidden under FMA loop)
#pragma unroll
            for (int k = 0; k < 4; k++)
                pa[k] = E4[(i0 + ar) * 64 + (ch + 1) * 8 + ah + 2 * k];
#pragma unroll
            for (int k = 0; k < 2; k++)
                pb[k] = E4[(j0 + br) * 64 + (ch + 1) * 8 + bh + 4 * k];
        }

#pragma unroll
        for (int d = 0; d < 32; d++) {
            uint64_t a01, a23;
            asm("ld.shared.v2.u64 {%0, %1}, [%2];"
                : "=l"(a01), "=l"(a23) : "r"(as_base + d * (68 * 4)));
            uint32_t b0, b1, b2, b3;
            asm("ld.shared.v4.b32 {%0, %1, %2, %3}, [%4];"
                : "=r"(b0), "=r"(b1), "=r"(b2), "=r"(b3)
                : "r"(bs_base + d * (36 * 4)));
            uint64_t bb0, bb1, bb2, bb3;
            asm("mov.b64 %0, {%1, %1};" : "=l"(bb0) : "r"(b0));
            asm("mov.b64 %0, {%1, %1};" : "=l"(bb1) : "r"(b1));
            asm("mov.b64 %0, {%1, %1};" : "=l"(bb2) : "r"(b2));
            asm("mov.b64 %0, {%1, %1};" : "=l"(bb3) : "r"(b3));
            FMA2(accP[0], a01, bb0);
            FMA2(accP[1], a01, bb1);
            FMA2(accP[2], a01, bb2);
            FMA2(accP[3], a01, bb3);
            FMA2(accQ[0], a23, bb0);
            FMA2(accQ[1], a23, bb1);
            FMA2(accQ[2], a23, bb2);
            FMA2(accQ[3], a23, bb3);
        }
        __syncthreads();
    }

    // publish row norms
    nA += __shfl_xor_sync(0xffffffffu, nA, 1);
    if (ah == 0) sni[ar] = nA;
    nB += __shfl_xor_sync(0xffffffffu, nB, 1);
    nB += __shfl_xor_sync(0xffffffffu, nB, 2);
    if (bh == 0) snj[br] = nB;
    __syncthreads();

    // unpack dots: dt[r][c]
    float dt[4][4];
#pragma unroll
    for (int c = 0; c < 4; c++) {
        uint32_t lo, hi;
        asm("mov.b64 {%0, %1}, %2;" : "=r"(lo), "=r"(hi) : "l"(accP[c]));
        dt[0][c] = __uint_as_float(lo); dt[1][c] = __uint_as_float(hi);
        asm("mov.b64 {%0, %1}, %2;" : "=r"(lo), "=r"(hi) : "l"(accQ[c]));
        dt[2][c] = __uint_as_float(lo); dt[3][c] = __uint_as_float(hi);
    }

    float njv[4]; int ljv[4];
#pragma unroll
    for (int c = 0; c < 4; c++) { njv[c] = snj[4 * tx + c]; ljv[c] = slj[4 * tx + c]; }

#pragma unroll
    for (int r = 0; r < 4; r++) {
        const int gi = i0 + 4 * ty + r;
        const int la = sli[4 * ty + r];
        const float nir = sni[4 * ty + r];

        unsigned long long bp = 0ull;   // pos: max dist, same label, j!=i; tie -> low j
        unsigned long long bn = ~0ull;  // neg: min dist, diff label; tie -> low j
#pragma unroll
        for (int c = 0; c < 4; c++) {
            const int jg = j0 + 4 * tx + c;
            float dist = sqrtf(fmaxf(nir + njv[c] - 2.f * dt[r][c], 0.f)) + EPSF;
            unsigned long long enc = ((unsigned long long)__float_as_uint(dist) << 32);
            if (ljv[c] == la && jg != gi) {
                unsigned long long cnd = enc | (0xFFFFFFFFu - (unsigned)jg);
                if (cnd > bp) bp = cnd;
            }
            if (ljv[c] != la) {
                unsigned long long cnd = enc | (unsigned)jg;
                if (cnd < bn) bn = cnd;
            }
        }
#pragma unroll
        for (int off = 4; off; off >>= 1) {
            unsigned long long o = __shfl_down_sync(0xffffffffu, bp, off, 8);
            if (o > bp) bp = o;
            o = __shfl_down_sync(0xffffffffu, bn, off, 8);
            if (o < bn) bn = o;
        }
        if (tx == 0) {
            g_pos[gi * 16 + blockIdx.x] = bp;
            g_neg[gi * 16 + blockIdx.x] = bn;
        }
    }
}

// ---------------------------------------------------------------------------
// K2: combine candidates, dist_unc at selected pairs, loss, last-block finish.
//     grid 128 x 4 anchors, 256 threads.
// ---------------------------------------------------------------------------
__global__ __launch_bounds__(256) void k_finalize(const float* __restrict__ E,
                                                  const float* __restrict__ U,
                                                  float* __restrict__ out) {
    const int t = threadIdx.x;
    const int bid = blockIdx.x;
    const int i0 = bid * 4;
    const int w = t >> 5, lane = t & 31;

    __shared__ int   s_j[8];
    __shared__ float s_d[8];
    __shared__ int   s_v[8];
    __shared__ float s_w[8];
    __shared__ float s_us[4];
    __shared__ float s_al[4], s_av[4];
    __shared__ int   s_islast;
    __shared__ float s_red[12];

    // phase A: warp w combines 16 tile partials for (anchor w/2, side w&1)
    {
        const int a = w >> 1, side = w & 1;
        const int ia = i0 + a;
        unsigned long long p;
        if (side == 0) p = (lane < 16) ? g_pos[ia * 16 + lane] : 0ull;
        else           p = (lane < 16) ? g_neg[ia * 16 + lane] : ~0ull;
#pragma unroll
        for (int off = 16; off; off >>= 1) {
            unsigned long long o = __shfl_down_sync(0xffffffffu, p, off);
            if (side == 0) { if (o > p) p = o; }
            else           { if (o < p) p = o; }
        }
        if (lane == 0) {
            bool valid = (side == 0) ? (p != 0ull) : (p != ~0ull);
            s_v[w] = valid ? 1 : 0;
            s_d[w] = __uint_as_float((uint32_t)(p >> 32));
            s_j[w] = valid ? ((side == 0) ? (int)(0xFFFFFFFFu - (uint32_t)p)
                                          : (int)(uint32_t)p)
                           : 0;
        }
    }
    __syncthreads();

    // phase B: warp w -> W = sum_d u_i^2 (e_i - e_j)^2 (float4 loads);
    //          side-0 warp also sums clipped u over the anchor row.
    {
        const int a = w >> 1;
        const int ia = i0 + a;
        const int jx = s_j[w];
        const float4* U4 = (const float4*)U;
        const float4* E4 = (const float4*)E;
        float4 ua = U4[ia * 64 + 2 * lane];
        float4 ub = U4[ia * 64 + 2 * lane + 1];
        float4 ea = E4[ia * 64 + 2 * lane];
        float4 eb = E4[ia * 64 + 2 * lane + 1];
        float4 ja = E4[jx * 64 + 2 * lane];
        float4 jb = E4[jx * 64 + 2 * lane + 1];
        // clip (NaN -> 1e-6 via fmaxf semantics, Inf -> 1)
        ua.x = fminf(fmaxf(ua.x, 1e-6f), 1.f); ua.y = fminf(fmaxf(ua.y, 1e-6f), 1.f);
        ua.z = fminf(fmaxf(ua.z, 1e-6f), 1.f); ua.w = fminf(fmaxf(ua.w, 1e-6f), 1.f);
        ub.x = fminf(fmaxf(ub.x, 1e-6f), 1.f); ub.y = fminf(fmaxf(ub.y, 1e-6f), 1.f);
        ub.z = fminf(fmaxf(ub.z, 1e-6f), 1.f); ub.w = fminf(fmaxf(ub.w, 1e-6f), 1.f);
        float W = 0.f;
        float dfx;
        dfx = ea.x - ja.x; W = fmaf(ua.x * ua.x, dfx * dfx, W);
        dfx = ea.y - ja.y; W = fmaf(ua.y * ua.y, dfx * dfx, W);
        dfx = ea.z - ja.z; W = fmaf(ua.z * ua.z, dfx * dfx, W);
        dfx = ea.w - ja.w; W = fmaf(ua.w * ua.w, dfx * dfx, W);
        dfx = eb.x - jb.x; W = fmaf(ub.x * ub.x, dfx * dfx, W);
        dfx = eb.y - jb.y; W = fmaf(ub.y * ub.y, dfx * dfx, W);
        dfx = eb.z - jb.z; W = fmaf(ub.z * ub.z, dfx * dfx, W);
        dfx = eb.w - jb.w; W = fmaf(ub.w * ub.w, dfx * dfx, W);
        float us = ((ua.x + ua.y) + (ua.z + ua.w)) + ((ub.x + ub.y) + (ub.z + ub.w));
#pragma unroll
        for (int off = 16; off; off >>= 1) {
            W  += __shfl_down_sync(0xffffffffu, W, off);
            us += __shfl_down_sync(0xffffffffu, us, off);
        }
        if (lane == 0) {
            s_w[w] = W;
            if ((w & 1) == 0) s_us[a] = us;
        }
    }
    __syncthreads();

    // phase C: per-anchor loss
    if (t < 4) {
        const int a = t;
        float dp = s_d[2 * a], dn = s_d[2 * a + 1];
        bool valid = s_v[2 * a] && s_v[2 * a + 1];
        float wp = s_w[2 * a], wn = s_w[2 * a + 1];
        float up2 = wp / (dp * dp) + EPSF;
        float un2 = wn / (dn * dn) + EPSF;
        float sig = sqrtf(up2 + un2 + EPSF);
        float me = MARGINF + UWF * sig;
        float z = (dp - dn + me) / sig;
        float sp = fmaxf(z, 0.f) + log1pf(expf(-fabsf(z)));
        s_al[a] = valid ? sig * sp : 0.f;
        s_av[a] = valid ? 1.f : 0.f;
    }
    __syncthreads();

    if (t == 0) {
        g_bl[bid] = s_al[0] + s_al[1] + s_al[2] + s_al[3];
        g_bv[bid] = s_av[0] + s_av[1] + s_av[2] + s_av[3];
        g_bu[bid] = s_us[0] + s_us[1] + s_us[2] + s_us[3];
        __threadfence();
        s_islast = (atomicInc(&g_ctr, 127) == 127) ? 1 : 0;
    }
    __syncthreads();

    if (s_islast) {
        __threadfence();
        float l = 0.f, v = 0.f, u = 0.f;
        if (t < 128) { l = g_bl[t]; v = g_bv[t]; u = g_bu[t]; }
#pragma unroll
        for (int off = 16; off; off >>= 1) {
            l += __shfl_down_sync(0xffffffffu, l, off);
            v += __shfl_down_sync(0xffffffffu, v, off);
            u += __shfl_down_sync(0xffffffffu, u, off);
        }
        if (lane == 0 && w < 4) {
            s_red[w] = l; s_red[4 + w] = v; s_red[8 + w] = u;
        }
        __syncthreads();
        if (t == 0) {
            float L = (s_red[0] + s_red[1]) + (s_red[2] + s_red[3]);
            float V = (s_red[4] + s_red[5]) + (s_red[6] + s_red[7]);
            float Uu = (s_red[8] + s_red[9]) + (s_red[10] + s_red[11]);
            float total = L / fmaxf(V, 1.0f) + UWF * (Uu / (float)(BSZ * DSZ));
            if (isnan(total) || isinf(total)) total = 0.f;
            out[0] = total;
        }
    }
}

// ---------------------------------------------------------------------------
extern "C" void kernel_launch(void* const* d_in, const int* in_sizes, int n_in,
                              void* d_out, int out_size) {
    const float* E = (const float*)d_in[0];
    const float* U = (const float*)d_in[1];
    const int*   L = (const int*)d_in[2];
    float* out = (float*)d_out;

    k_dist_mine<<<dim3(16, 8), 128>>>(E, L);
    k_finalize<<<128, 256>>>(E, U, out);
}